// round 4
// baseline (speedup 1.0000x reference)
#include <cuda_runtime.h>

// Problem constants
#define TT 1024
#define BBATCH 4
#define EE 1024
#define HH 16
#define NBH 64              // B*H
#define MROWS 4096          // T*B
#define SCALE_Q 0.125f      // HD^-0.5, HD=64
#define SEG 4194304         // T*B*E elements per output segment

// ---------------- scratch (__device__ globals; no allocations) ----------------
__device__ float g_q[(size_t)NBH * TT * 128];      // [bh][t][ qr*s (64) | qi*s (64) ]
__device__ float g_k[(size_t)NBH * TT * 128];      // [bh][t][ kr+ki | kr-ki ]
__device__ float g_v[(size_t)NBH * TT * 128];      // [bh][t][ vr | vi ]
__device__ float g_aw[(size_t)NBH * TT * TT];      // raw awr, 256 MB
__device__ float g_attn_re[(size_t)MROWS * EE];    // attn real, (t*B+b, e)
__device__ float g_attn_im[(size_t)MROWS * EE];    // attn imag
__device__ float g_minmax[2];                      // [min, max]
__device__ float g_ms[2];                          // [min, 1/(max-min)]

// ---------------- helpers ----------------
__device__ __forceinline__ void atomicMinF(float* addr, float val) {
    int old = __float_as_int(*addr);
    while (val < __int_as_float(old)) {
        int assumed = old;
        old = atomicCAS((int*)addr, assumed, __float_as_int(val));
        if (old == assumed) break;
    }
}
__device__ __forceinline__ void atomicMaxF(float* addr, float val) {
    int old = __float_as_int(*addr);
    while (val > __int_as_float(old)) {
        int assumed = old;
        old = atomicCAS((int*)addr, assumed, __float_as_int(val));
        if (old == assumed) break;
    }
}

__global__ void k_init() {
    g_minmax[0] = __int_as_float(0x7f800000);   // +inf
    g_minmax[1] = __int_as_float(0xff800000);   // -inf
}

__global__ void k_scale() {
    float mn = g_minmax[0], mx = g_minmax[1];
    g_ms[0] = mn;
    g_ms[1] = 1.0f / (mx - mn);
}

// ---------------- K1: complex input projection ----------------
// C(4096,3072) = X(4096,1024) @ W(3072,1024)^T + b   (complex)
// Epilogue scatters into g_q / g_k / g_v packed layouts.
__global__ __launch_bounds__(256, 1) void k_proj(
    const float* __restrict__ xr, const float* __restrict__ xi,
    const float* __restrict__ wr, const float* __restrict__ wi,
    const float* __restrict__ br, const float* __restrict__ bi)
{
    __shared__ float Asr[8][128], Asi[8][128], Bsr[8][128], Bsi[8][128];
    const int tid = threadIdx.x;
    const int tx = tid & 15, ty = tid >> 4;
    const int bm = blockIdx.y * 128;
    const int bn = blockIdx.x * 128;
    const int lr = tid >> 1;
    const int lk = (tid & 1) * 4;

    float cr[8][8] = {}, ci[8][8] = {};

    const float* pxr = xr + (size_t)(bm + lr) * EE + lk;
    const float* pxi = xi + (size_t)(bm + lr) * EE + lk;
    const float* pwr = wr + (size_t)(bn + lr) * EE + lk;
    const float* pwi = wi + (size_t)(bn + lr) * EE + lk;

    for (int kt = 0; kt < EE; kt += 8) {
        float4 a0 = *(const float4*)(pxr + kt);
        float4 a1 = *(const float4*)(pxi + kt);
        float4 b0 = *(const float4*)(pwr + kt);
        float4 b1 = *(const float4*)(pwi + kt);
        __syncthreads();
        Asr[lk+0][lr]=a0.x; Asr[lk+1][lr]=a0.y; Asr[lk+2][lr]=a0.z; Asr[lk+3][lr]=a0.w;
        Asi[lk+0][lr]=a1.x; Asi[lk+1][lr]=a1.y; Asi[lk+2][lr]=a1.z; Asi[lk+3][lr]=a1.w;
        Bsr[lk+0][lr]=b0.x; Bsr[lk+1][lr]=b0.y; Bsr[lk+2][lr]=b0.z; Bsr[lk+3][lr]=b0.w;
        Bsi[lk+0][lr]=b1.x; Bsi[lk+1][lr]=b1.y; Bsi[lk+2][lr]=b1.z; Bsi[lk+3][lr]=b1.w;
        __syncthreads();
        #pragma unroll
        for (int k = 0; k < 8; k++) {
            float ar[8], ai[8], bre[8], bim[8];
            #pragma unroll
            for (int i = 0; i < 8; i++) { ar[i] = Asr[k][ty*8+i]; ai[i] = Asi[k][ty*8+i]; }
            #pragma unroll
            for (int j = 0; j < 8; j++) { bre[j] = Bsr[k][tx*8+j]; bim[j] = Bsi[k][tx*8+j]; }
            #pragma unroll
            for (int i = 0; i < 8; i++)
                #pragma unroll
                for (int j = 0; j < 8; j++) {
                    cr[i][j] += ar[i]*bre[j] - ai[i]*bim[j];
                    ci[i][j] += ar[i]*bim[j] + ai[i]*bre[j];
                }
        }
    }

    const int seg = bn >> 10;   // 0=q, 1=k, 2=v (block never straddles)
    #pragma unroll
    for (int i = 0; i < 8; i++) {
        int m = bm + ty*8 + i;
        int t = m >> 2, bb = m & 3;
        #pragma unroll
        for (int j = 0; j < 8; j++) {
            int n = bn + tx*8 + j;
            float vr = cr[i][j] + br[n];
            float vi = ci[i][j] + bi[n];
            int nn = n & 1023;
            int h = nn >> 6, hd = nn & 63;
            size_t base = ((size_t)(bb * HH + h) * TT + t) * 128;
            if (seg == 0)      { g_q[base + hd] = vr * SCALE_Q; g_q[base + 64 + hd] = vi * SCALE_Q; }
            else if (seg == 1) { g_k[base + hd] = vr + vi;      g_k[base + 64 + hd] = vr - vi; }
            else               { g_v[base + hd] = vr;           g_v[base + 64 + hd] = vi; }
        }
    }
}

// ---------------- K2: per-head QK^T (real, K=128) + global min/max ----------------
__global__ __launch_bounds__(256, 2) void k_qk()
{
    __shared__ float As[8][128], Bs[8][128];
    __shared__ float smn[8], smx[8];
    const int tid = threadIdx.x;
    const int tx = tid & 15, ty = tid >> 4;
    const int bh = blockIdx.z;
    const int bm = blockIdx.y * 128;
    const int bn = blockIdx.x * 128;
    const int lr = tid >> 1;
    const int lk = (tid & 1) * 4;

    const float* A  = g_q + (size_t)bh * TT * 128;
    const float* Bp = g_k + (size_t)bh * TT * 128;

    float c[8][8] = {};
    for (int kt = 0; kt < 128; kt += 8) {
        float4 a0 = *(const float4*)(A  + (size_t)(bm + lr) * 128 + kt + lk);
        float4 b0 = *(const float4*)(Bp + (size_t)(bn + lr) * 128 + kt + lk);
        __syncthreads();
        As[lk+0][lr]=a0.x; As[lk+1][lr]=a0.y; As[lk+2][lr]=a0.z; As[lk+3][lr]=a0.w;
        Bs[lk+0][lr]=b0.x; Bs[lk+1][lr]=b0.y; Bs[lk+2][lr]=b0.z; Bs[lk+3][lr]=b0.w;
        __syncthreads();
        #pragma unroll
        for (int k = 0; k < 8; k++) {
            float a[8], b[8];
            #pragma unroll
            for (int i = 0; i < 8; i++) a[i] = As[k][ty*8+i];
            #pragma unroll
            for (int j = 0; j < 8; j++) b[j] = Bs[k][tx*8+j];
            #pragma unroll
            for (int i = 0; i < 8; i++)
                #pragma unroll
                for (int j = 0; j < 8; j++)
                    c[i][j] += a[i] * b[j];
        }
    }

    float mn = __int_as_float(0x7f800000), mx = __int_as_float(0xff800000);
    float* C = g_aw + (size_t)bh * TT * TT;
    #pragma unroll
    for (int i = 0; i < 8; i++) {
        size_t row = (size_t)(bm + ty*8 + i) * TT + bn + tx*8;
        #pragma unroll
        for (int j = 0; j < 8; j++) {
            float v = c[i][j];
            C[row + j] = v;
            mn = fminf(mn, v); mx = fmaxf(mx, v);
        }
    }
    // block reduce min/max
    const int lane = tid & 31, wid = tid >> 5;
    #pragma unroll
    for (int off = 16; off; off >>= 1) {
        mn = fminf(mn, __shfl_down_sync(0xffffffffu, mn, off));
        mx = fmaxf(mx, __shfl_down_sync(0xffffffffu, mx, off));
    }
    if (lane == 0) { smn[wid] = mn; smx[wid] = mx; }
    __syncthreads();
    if (tid == 0) {
        #pragma unroll
        for (int w = 1; w < 8; w++) { mn = fminf(mn, smn[w]); mx = fmaxf(mx, smx[w]); }
        atomicMinF(&g_minmax[0], mn);
        atomicMaxF(&g_minmax[1], mx);
    }
}

// ---------------- K4: per-head attn = norm(awr) @ [vr|vi] ----------------
__global__ __launch_bounds__(256, 2) void k_av()
{
    __shared__ float As[8][128], Bs[8][128];
    const int tid = threadIdx.x;
    const int tx = tid & 15, ty = tid >> 4;
    const int bm = blockIdx.x * 128;
    const int bh = blockIdx.y;
    const float mn = g_ms[0], sc = g_ms[1];

    const float* A = g_aw + (size_t)bh * TT * TT;
    const float* V = g_v  + (size_t)bh * TT * 128;

    const int lr = tid >> 1, lk = (tid & 1) * 4;    // A tile loader
    const int vkr = tid >> 5, vn = (tid & 31) * 4;  // B tile loader (8x128, direct)

    float c[8][8] = {};
    for (int kt = 0; kt < TT; kt += 8) {
        float4 a0 = *(const float4*)(A + (size_t)(bm + lr) * TT + kt + lk);
        float4 b0 = *(const float4*)(V + (size_t)(kt + vkr) * 128 + vn);
        a0.x = (a0.x - mn) * sc; a0.y = (a0.y - mn) * sc;
        a0.z = (a0.z - mn) * sc; a0.w = (a0.w - mn) * sc;
        __syncthreads();
        As[lk+0][lr]=a0.x; As[lk+1][lr]=a0.y; As[lk+2][lr]=a0.z; As[lk+3][lr]=a0.w;
        *(float4*)&Bs[vkr][vn] = b0;
        __syncthreads();
        #pragma unroll
        for (int k = 0; k < 8; k++) {
            float a[8], b[8];
            #pragma unroll
            for (int i = 0; i < 8; i++) a[i] = As[k][ty*8+i];
            #pragma unroll
            for (int j = 0; j < 8; j++) b[j] = Bs[k][tx*8+j];
            #pragma unroll
            for (int i = 0; i < 8; i++)
                #pragma unroll
                for (int j = 0; j < 8; j++)
                    c[i][j] += a[i] * b[j];
        }
    }

    const int bb = bh >> 4, h = bh & 15;
    #pragma unroll
    for (int i = 0; i < 8; i++) {
        int q = bm + ty*8 + i;
        size_t m = (size_t)q * BBATCH + bb;
        #pragma unroll
        for (int j = 0; j < 8; j++) {
            int n = tx*8 + j;
            int e = h * 64 + (n & 63);
            if (n < 64) g_attn_re[m * EE + e] = c[i][j];
            else        g_attn_im[m * EE + e] = c[i][j];
        }
    }
}

// ---------------- K5: aw_avg = (mean_h awr_raw - min) * scale ----------------
__global__ void k_avg(float* __restrict__ out)
{
    size_t idx = (size_t)blockIdx.x * 256 + threadIdx.x;   // over 4*1024*1024
    int b = (int)(idx >> 20);
    size_t qk = idx & 0xFFFFFu;
    float s = 0.f;
    #pragma unroll
    for (int h = 0; h < HH; h++)
        s += g_aw[(((size_t)(b * HH + h)) << 20) + qk];
    out[idx] = (s * (1.0f / HH) - g_ms[0]) * g_ms[1];
}

// ---------------- K6: complex output projection ----------------
__global__ __launch_bounds__(256, 1) void k_oproj(
    const float* __restrict__ owr, const float* __restrict__ owi,
    const float* __restrict__ obr, const float* __restrict__ obi,
    float* __restrict__ outre, float* __restrict__ outim)
{
    __shared__ float Asr[8][128], Asi[8][128], Bsr[8][128], Bsi[8][128];
    const int tid = threadIdx.x;
    const int tx = tid & 15, ty = tid >> 4;
    const int bm = blockIdx.y * 128;
    const int bn = blockIdx.x * 128;
    const int lr = tid >> 1;
    const int lk = (tid & 1) * 4;

    float cr[8][8] = {}, ci[8][8] = {};

    const float* par = g_attn_re + (size_t)(bm + lr) * EE + lk;
    const float* pai = g_attn_im + (size_t)(bm + lr) * EE + lk;
    const float* pwr = owr + (size_t)(bn + lr) * EE + lk;
    const float* pwi = owi + (size_t)(bn + lr) * EE + lk;

    for (int kt = 0; kt < EE; kt += 8) {
        float4 a0 = *(const float4*)(par + kt);
        float4 a1 = *(const float4*)(pai + kt);
        float4 b0 = *(const float4*)(pwr + kt);
        float4 b1 = *(const float4*)(pwi + kt);
        __syncthreads();
        Asr[lk+0][lr]=a0.x; Asr[lk+1][lr]=a0.y; Asr[lk+2][lr]=a0.z; Asr[lk+3][lr]=a0.w;
        Asi[lk+0][lr]=a1.x; Asi[lk+1][lr]=a1.y; Asi[lk+2][lr]=a1.z; Asi[lk+3][lr]=a1.w;
        Bsr[lk+0][lr]=b0.x; Bsr[lk+1][lr]=b0.y; Bsr[lk+2][lr]=b0.z; Bsr[lk+3][lr]=b0.w;
        Bsi[lk+0][lr]=b1.x; Bsi[lk+1][lr]=b1.y; Bsi[lk+2][lr]=b1.z; Bsi[lk+3][lr]=b1.w;
        __syncthreads();
        #pragma unroll
        for (int k = 0; k < 8; k++) {
            float ar[8], ai[8], bre[8], bim[8];
            #pragma unroll
            for (int i = 0; i < 8; i++) { ar[i] = Asr[k][ty*8+i]; ai[i] = Asi[k][ty*8+i]; }
            #pragma unroll
            for (int j = 0; j < 8; j++) { bre[j] = Bsr[k][tx*8+j]; bim[j] = Bsi[k][tx*8+j]; }
            #pragma unroll
            for (int i = 0; i < 8; i++)
                #pragma unroll
                for (int j = 0; j < 8; j++) {
                    cr[i][j] += ar[i]*bre[j] - ai[i]*bim[j];
                    ci[i][j] += ar[i]*bim[j] + ai[i]*bre[j];
                }
        }
    }

    #pragma unroll
    for (int i = 0; i < 8; i++) {
        size_t m = (size_t)(bm + ty*8 + i);
        #pragma unroll
        for (int j = 0; j < 8; j++) {
            int n = bn + tx*8 + j;
            outre[m * EE + n] = cr[i][j] + obr[n];
            outim[m * EE + n] = ci[i][j] + obi[n];
        }
    }
}

// ---------------- launch ----------------
extern "C" void kernel_launch(void* const* d_in, const int* in_sizes, int n_in,
                              void* d_out, int out_size)
{
    const float* xr  = (const float*)d_in[0];
    const float* xi  = (const float*)d_in[1];
    const float* wr  = (const float*)d_in[2];
    const float* wi  = (const float*)d_in[3];
    const float* br  = (const float*)d_in[4];
    const float* bi  = (const float*)d_in[5];
    const float* owr = (const float*)d_in[6];
    const float* owi = (const float*)d_in[7];
    const float* obr = (const float*)d_in[8];
    const float* obi = (const float*)d_in[9];
    float* out = (float*)d_out;

    k_init<<<1, 1>>>();
    k_proj<<<dim3(24, 32), 256>>>(xr, xi, wr, wi, br, bi);
    k_qk<<<dim3(8, 8, 64), 256>>>();
    k_scale<<<1, 1>>>();
    k_av<<<dim3(8, 64), 256>>>();
    k_avg<<<16384, 256>>>(out + 2 * (size_t)SEG);
    k_oproj<<<dim3(8, 32), 256>>>(owr, owi, obr, obi, out, out + SEG);
}

// round 6
// speedup vs baseline: 2.7335x; 2.7335x over previous
#include <cuda_runtime.h>
#include <cuda_bf16.h>
#include <cstdint>

#define SEG 4194304
#define SCALE_Q 0.125f

// ---------------- scratch (__device__ globals; no allocations) ----------------
__device__ __align__(256) __nv_bfloat16 g_xh[4096*2048], g_xl[4096*2048];
__device__ __align__(256) __nv_bfloat16 g_wh[6144*2048], g_wl[6144*2048];
__device__ __align__(256) __nv_bfloat16 g_owh[2048*2048], g_owl[2048*2048];
__device__ __align__(256) float g_c1[(size_t)4096*6144];
__device__ __align__(256) __nv_bfloat16 g_qh[64*1024*128], g_ql[64*1024*128];
__device__ __align__(256) __nv_bfloat16 g_kh[64*1024*128], g_kl[64*1024*128];
__device__ __align__(256) __nv_bfloat16 g_vth[64*128*1024], g_vtl[64*128*1024];
__device__ __align__(256) float g_aw[(size_t)64*1024*1024];
__device__ __align__(256) __nv_bfloat16 g_awh[(size_t)64*1024*1024];
__device__ __align__(256) __nv_bfloat16 g_awl[(size_t)64*1024*1024];
__device__ __align__(256) float g_attn[(size_t)4096*2048];
__device__ __align__(256) __nv_bfloat16 g_a2h[4096*2048], g_a2l[4096*2048];
__device__ float g_minmax[2];
__device__ float g_ms[2];

// ---------------- helpers ----------------
__device__ __forceinline__ uint32_t s2u(const void* p) {
    uint32_t a;
    asm("{ .reg .u64 t; cvta.to.shared.u64 t, %1; cvt.u32.u64 %0, t; }" : "=r"(a) : "l"(p));
    return a;
}
__device__ __forceinline__ void cpa16(uint32_t d, const void* s) {
    asm volatile("cp.async.cg.shared.global [%0], [%1], 16;" :: "r"(d), "l"(s));
}
#define CP_COMMIT() asm volatile("cp.async.commit_group;")
#define CP_WAIT(n)  asm volatile("cp.async.wait_group %0;" :: "n"(n))

#define LDM4(r0, r1, r2, r3, a) \
    asm volatile("ldmatrix.sync.aligned.m8n8.x4.shared.b16 {%0,%1,%2,%3}, [%4];" \
                 : "=r"(r0), "=r"(r1), "=r"(r2), "=r"(r3) : "r"(a))

#define MMA16816(c, a, b) \
    asm volatile("mma.sync.aligned.m16n8k16.row.col.f32.bf16.bf16.f32 " \
                 "{%0,%1,%2,%3}, {%4,%5,%6,%7}, {%8,%9}, {%0,%1,%2,%3};" \
                 : "+f"((c)[0]), "+f"((c)[1]), "+f"((c)[2]), "+f"((c)[3]) \
                 : "r"((a)[0]), "r"((a)[1]), "r"((a)[2]), "r"((a)[3]), \
                   "r"((b)[0]), "r"((b)[1]))

__device__ __forceinline__ uint32_t pk(__nv_bfloat16 a, __nv_bfloat16 b) {
    __nv_bfloat162 t = __halves2bfloat162(a, b);
    return *reinterpret_cast<uint32_t*>(&t);
}
__device__ __forceinline__ void bsplit_store(__nv_bfloat16* H, __nv_bfloat16* L, size_t i, float v) {
    __nv_bfloat16 h = __float2bfloat16(v);
    H[i] = h;
    L[i] = __float2bfloat16(v - __bfloat162float(h));
}
__device__ __forceinline__ void atomicMinF(float* addr, float val) {
    int old = __float_as_int(*addr);
    while (val < __int_as_float(old)) {
        int assumed = old;
        old = atomicCAS((int*)addr, assumed, __float_as_int(val));
        if (old == assumed) break;
    }
}
__device__ __forceinline__ void atomicMaxF(float* addr, float val) {
    int old = __float_as_int(*addr);
    while (val > __int_as_float(old)) {
        int assumed = old;
        old = atomicCAS((int*)addr, assumed, __float_as_int(val));
        if (old == assumed) break;
    }
}

__global__ void k_init() {
    g_minmax[0] = __int_as_float(0x7f800000);
    g_minmax[1] = __int_as_float(0xff800000);
}
__global__ void k_scale() {
    float mn = g_minmax[0], mx = g_minmax[1];
    g_ms[0] = mn;
    g_ms[1] = 1.0f / (mx - mn);
}

// ---------------- prep kernels ----------------
__global__ void k_prep_x(const float* __restrict__ xr, const float* __restrict__ xi) {
    int idx = blockIdx.x * 256 + threadIdx.x;   // 4096*2048
    int m = idx >> 11, k = idx & 2047;
    float v = (k < 1024) ? xr[m * 1024 + k] : xi[m * 1024 + k - 1024];
    bsplit_store(g_xh, g_xl, idx, v);
}
__global__ void k_prep_w(const float* __restrict__ wr, const float* __restrict__ wi) {
    int idx = blockIdx.x * 256 + threadIdx.x;   // 6144*2048
    int p = idx >> 11, k = idx & 2047;
    int n = p >> 1;
    float v;
    if (!(p & 1)) v = (k < 1024) ? wr[n * 1024 + k] : -wi[n * 1024 + k - 1024];
    else          v = (k < 1024) ? wi[n * 1024 + k] :  wr[n * 1024 + k - 1024];
    bsplit_store(g_wh, g_wl, idx, v);
}
__global__ void k_prep_ow(const float* __restrict__ owr, const float* __restrict__ owi) {
    int idx = blockIdx.x * 256 + threadIdx.x;   // 2048*2048
    int p = idx >> 11, k = idx & 2047;
    int n = p >> 1;
    float v;
    if (!(p & 1)) v = (k < 1024) ? owr[n * 1024 + k] : -owi[n * 1024 + k - 1024];
    else          v = (k < 1024) ? owi[n * 1024 + k] :  owr[n * 1024 + k - 1024];
    bsplit_store(g_owh, g_owl, idx, v);
}

// ---------------- transforms ----------------
__global__ void k_trans_qk(const float* __restrict__ br, const float* __restrict__ bi) {
    int idx = blockIdx.x * 256 + threadIdx.x;   // 64*1024*64
    int hd = idx & 63, t = (idx >> 6) & 1023, bh = idx >> 16;
    int b = bh >> 4, h = bh & 15;
    size_t m = (size_t)t * 4 + b;
    int nq = h * 64 + hd;
    const float* cr = g_c1 + m * 6144;
    float qr = cr[2*nq]        + br[nq],      qi = cr[2*nq+1]        + bi[nq];
    float kr = cr[2*(nq+1024)] + br[nq+1024], ki = cr[2*(nq+1024)+1] + bi[nq+1024];
    size_t base = ((size_t)bh * 1024 + t) * 128;
    bsplit_store(g_qh, g_ql, base + hd,      qr * SCALE_Q);
    bsplit_store(g_qh, g_ql, base + 64 + hd, qi * SCALE_Q);
    bsplit_store(g_kh, g_kl, base + hd,      kr + ki);
    bsplit_store(g_kh, g_kl, base + 64 + hd, kr - ki);
}

__global__ void k_trans_v(const float* __restrict__ br, const float* __restrict__ bi) {
    __shared__ float sv[64][129];
    int bh = blockIdx.y, tblk = blockIdx.x;
    int b = bh >> 4, h = bh & 15;
    for (int i = threadIdx.x; i < 8192; i += 256) {
        int tl = i >> 7, n = i & 127;
        int hd = n & 63;
        int im = (n >= 64);
        size_t m = (size_t)(tblk * 64 + tl) * 4 + b;
        int nv = 2048 + h * 64 + hd;
        sv[tl][n] = g_c1[m * 6144 + 2 * nv + im] + (im ? bi[nv] : br[nv]);
    }
    __syncthreads();
    for (int i = threadIdx.x; i < 8192; i += 256) {
        int n = i >> 6, tl = i & 63;
        size_t o = ((size_t)bh * 128 + n) * 1024 + tblk * 64 + tl;
        bsplit_store(g_vth, g_vtl, o, sv[tl][n]);
    }
}

__global__ void k_norm_aw() {
    size_t i4 = ((size_t)blockIdx.x * 256 + threadIdx.x) * 4;   // 64Mi elems
    float4 v = *(const float4*)(g_aw + i4);
    float mn = g_ms[0], sc = g_ms[1];
    v.x = (v.x - mn) * sc; v.y = (v.y - mn) * sc;
    v.z = (v.z - mn) * sc; v.w = (v.w - mn) * sc;
    __nv_bfloat16 h0 = __float2bfloat16(v.x), h1 = __float2bfloat16(v.y),
                  h2 = __float2bfloat16(v.z), h3 = __float2bfloat16(v.w);
    *(uint2*)(g_awh + i4) = make_uint2(pk(h0, h1), pk(h2, h3));
    *(uint2*)(g_awl + i4) = make_uint2(
        pk(__float2bfloat16(v.x - __bfloat162float(h0)), __float2bfloat16(v.y - __bfloat162float(h1))),
        pk(__float2bfloat16(v.z - __bfloat162float(h2)), __float2bfloat16(v.w - __bfloat162float(h3))));
}

__global__ void k_split_attn() {
    size_t i4 = ((size_t)blockIdx.x * 256 + threadIdx.x) * 4;   // 4096*2048
    float4 v = *(const float4*)(g_attn + i4);
    __nv_bfloat16 h0 = __float2bfloat16(v.x), h1 = __float2bfloat16(v.y),
                  h2 = __float2bfloat16(v.z), h3 = __float2bfloat16(v.w);
    *(uint2*)(g_a2h + i4) = make_uint2(pk(h0, h1), pk(h2, h3));
    *(uint2*)(g_a2l + i4) = make_uint2(
        pk(__float2bfloat16(v.x - __bfloat162float(h0)), __float2bfloat16(v.y - __bfloat162float(h1))),
        pk(__float2bfloat16(v.z - __bfloat162float(h2)), __float2bfloat16(v.w - __bfloat162float(h3))));
}

__global__ void k_avg(float* __restrict__ out) {
    size_t idx = (size_t)blockIdx.x * 256 + threadIdx.x;   // 4*1024*1024
    int b = (int)(idx >> 20);
    size_t qk = idx & 0xFFFFFu;
    float s = 0.f;
    #pragma unroll
    for (int h = 0; h < 16; h++)
        s += g_aw[(((size_t)(b * 16 + h)) << 20) + qk];
    out[idx] = (s * (1.0f / 16.0f) - g_ms[0]) * g_ms[1];
}

// ---------------- HMMA GEMM (mma.sync m16n8k16 bf16, split hi/lo x3) ----------------
// MODE 0: proj  A=g_x   B=g_w   C=g_c1            K=2048
// MODE 1: qk    A=g_q   B=g_k   C=g_aw + minmax   K=128,  z=head
// MODE 2: av    A=g_aw(hl) B=g_vt C=g_attn        K=1024, z=head
// MODE 3: oproj A=g_a2  B=g_ow  C=out re/im+bias  K=2048
// Tile 128x128, 8 warps (2x4), warp tile 64x32, K staged 32-wide, cp.async double buffer.
template<int MODE>
__global__ __launch_bounds__(256, 1) void k_gemm(
    const float* __restrict__ biasR, const float* __restrict__ biasI,
    float* __restrict__ outR, float* __restrict__ outI)
{
    extern __shared__ char sm[];
    const int tid = threadIdx.x, lane = tid & 31, wid = tid >> 5;
    const int wm = wid >> 2, wn = wid & 3;
    const int bm = blockIdx.y * 128, bn = blockIdx.x * 128, z = blockIdx.z;

    constexpr int ld = (MODE == 1) ? 128 : (MODE == 2) ? 1024 : 2048;
    constexpr int nk = (MODE == 1) ? 4 : (MODE == 2) ? 32 : 64;

    const __nv_bfloat16 *Ah, *Al, *Bh, *Bl;
    if (MODE == 0)      { Ah = g_xh;  Al = g_xl;  Bh = g_wh;  Bl = g_wl; }
    else if (MODE == 1) {
        Ah = g_qh + (size_t)z * 131072; Al = g_ql + (size_t)z * 131072;
        Bh = g_kh + (size_t)z * 131072; Bl = g_kl + (size_t)z * 131072;
    } else if (MODE == 2) {
        Ah = g_awh + ((size_t)z << 20); Al = g_awl + ((size_t)z << 20);
        Bh = g_vth + (size_t)z * 131072; Bl = g_vtl + (size_t)z * 131072;
    } else              { Ah = g_a2h; Al = g_a2l; Bh = g_owh; Bl = g_owl; }

    const uint32_t sb = s2u(sm);
    float acc[4][4][4] = {};

    // staging coords: 512 16B-segs per 8KB tile, 2 per thread
    const int srow = tid >> 1, sc0 = (tid & 1) * 2;

    // ldmatrix per-lane coords
    const int ra  = (lane & 7) + ((lane >> 3) & 1) * 8;   // A row within 16
    const int ksa = lane >> 4;                            // A k-seg (0/1)
    const int rb  = wn * 32 + ((lane >> 4) & 1) * 8 + (lane & 7);  // B row within warp n
    const int ksb = (lane >> 3) & 1;                      // B k-seg

    // ---- prologue: stage 0 ----
    {
        const __nv_bfloat16* srcs[4] = {Ah, Al, Bh, Bl};
        const int rbase[4] = {bm, bm, bn, bn};
        #pragma unroll
        for (int o = 0; o < 4; o++) {
            size_t g = (size_t)(rbase[o] + srow) * ld;
            uint32_t db = sb + o * 8192 + srow * 64;
            #pragma unroll
            for (int u = 0; u < 2; u++) {
                int c = sc0 + u;
                cpa16(db + ((c ^ ((srow >> 1) & 3)) << 4), srcs[o] + g + c * 8);
            }
        }
        CP_COMMIT();
    }

    for (int kt = 0; kt < nk; kt++) {
        if (kt + 1 < nk) {
            const int k0 = (kt + 1) * 32;
            const int buf = (kt + 1) & 1;
            const __nv_bfloat16* srcs[4] = {Ah, Al, Bh, Bl};
            const int rbase[4] = {bm, bm, bn, bn};
            #pragma unroll
            for (int o = 0; o < 4; o++) {
                size_t g = (size_t)(rbase[o] + srow) * ld + k0;
                uint32_t db = sb + buf * 32768 + o * 8192 + srow * 64;
                #pragma unroll
                for (int u = 0; u < 2; u++) {
                    int c = sc0 + u;
                    cpa16(db + ((c ^ ((srow >> 1) & 3)) << 4), srcs[o] + g + c * 8);
                }
            }
            CP_COMMIT();
            CP_WAIT(1);
        } else {
            CP_WAIT(0);
        }
        __syncthreads();

        // ---- compute on buffer kt&1 ----
        {
            const uint32_t base = sb + (kt & 1) * 32768;
            #pragma unroll
            for (int kk = 0; kk < 2; kk++) {
                uint32_t aH[4][4], aL[4][4], bH[4][2], bL[4][2];
                #pragma unroll
                for (int i = 0; i < 4; i++) {
                    int row = wm * 64 + i * 16 + ra;
                    int seg = kk * 2 + ksa;
                    uint32_t off = row * 64 + ((seg ^ ((row >> 1) & 3)) << 4);
                    LDM4(aH[i][0], aH[i][1], aH[i][2], aH[i][3], base + off);
                    LDM4(aL[i][0], aL[i][1], aL[i][2], aL[i][3], base + 8192 + off);
                }
                #pragma unroll
                for (int jj = 0; jj < 2; jj++) {
                    int row = rb + jj * 16;
                    int seg = kk * 2 + ksb;
                    uint32_t off = row * 64 + ((seg ^ ((row >> 1) & 3)) << 4);
                    LDM4(bH[2*jj][0], bH[2*jj][1], bH[2*jj+1][0], bH[2*jj+1][1], base + 16384 + off);
                    LDM4(bL[2*jj][0], bL[2*jj][1], bL[2*jj+1][0], bL[2*jj+1][1], base + 24576 + off);
                }
                #pragma unroll
                for (int i = 0; i < 4; i++)
                    #pragma unroll
                    for (int j = 0; j < 4; j++) {
                        MMA16816(acc[i][j], aH[i], bH[j]);
                        MMA16816(acc[i][j], aH[i], bL[j]);
                        MMA16816(acc[i][j], aL[i], bH[j]);
                    }
            }
        }
        __syncthreads();
    }

    // ---------------- epilogue ----------------
    float lmn = __int_as_float(0x7f800000), lmx = __int_as_float(0xff800000);
    #pragma unroll
    for (int i = 0; i < 4; i++) {
        const int r0 = bm + wm * 64 + i * 16 + (lane >> 2);
        #pragma unroll
        for (int j = 0; j < 4; j++) {
            const float* c = acc[i][j];
            const int n0 = wn * 32 + j * 8 + (lane & 3) * 2;   // local col
            if (MODE == 0) {
                *(float2*)(g_c1 + (size_t)r0 * 6144 + bn + n0)       = make_float2(c[0], c[1]);
                *(float2*)(g_c1 + (size_t)(r0 + 8) * 6144 + bn + n0) = make_float2(c[2], c[3]);
            } else if (MODE == 1) {
                float* Cz = g_aw + ((size_t)z << 20);
                *(float2*)(Cz + (size_t)r0 * 1024 + bn + n0)       = make_float2(c[0], c[1]);
                *(float2*)(Cz + (size_t)(r0 + 8) * 1024 + bn + n0) = make_float2(c[2], c[3]);
                lmn = fminf(lmn, fminf(fminf(c[0], c[1]), fminf(c[2], c[3])));
                lmx = fmaxf(lmx, fmaxf(fmaxf(c[0], c[1]), fmaxf(c[2], c[3])));
            } else if (MODE == 2) {
                const int b = z >> 4, h = z & 15;
                size_t e = (n0 < 64) ? (size_t)(h * 64 + n0) : (size_t)(1024 + h * 64 + n0 - 64);
                *(float2*)(g_attn + ((size_t)r0 * 4 + b) * 2048 + e)       = make_float2(c[0], c[1]);
                *(float2*)(g_attn + ((size_t)(r0 + 8) * 4 + b) * 2048 + e) = make_float2(c[2], c[3]);
            } else {
                const int nc = ((bn + n0) >> 1);   // complex col; c0/c2 re, c1/c3 im
                outR[(size_t)r0 * 1024 + nc]       = c[0] + biasR[nc];
                outI[(size_t)r0 * 1024 + nc]       = c[1] + biasI[nc];
                outR[(size_t)(r0 + 8) * 1024 + nc] = c[2] + biasR[nc];
                outI[(size_t)(r0 + 8) * 1024 + nc] = c[3] + biasI[nc];
            }
        }
    }
    if (MODE == 1) {
        #pragma unroll
        for (int off = 16; off; off >>= 1) {
            lmn = fminf(lmn, __shfl_xor_sync(0xffffffffu, lmn, off));
            lmx = fmaxf(lmx, __shfl_xor_sync(0xffffffffu, lmx, off));
        }
        float* red = (float*)sm;
        if (lane == 0) { red[wid] = lmn; red[8 + wid] = lmx; }
        __syncthreads();
        if (tid == 0) {
            float mn = red[0], mx = red[8];
            #pragma unroll
            for (int w = 1; w < 8; w++) { mn = fminf(mn, red[w]); mx = fmaxf(mx, red[8 + w]); }
            atomicMinF(&g_minmax[0], mn);
            atomicMaxF(&g_minmax[1], mx);
        }
    }
}

// ---------------- launch ----------------
extern "C" void kernel_launch(void* const* d_in, const int* in_sizes, int n_in,
                              void* d_out, int out_size)
{
    const float* xr  = (const float*)d_in[0];
    const float* xi  = (const float*)d_in[1];
    const float* wr  = (const float*)d_in[2];
    const float* wi  = (const float*)d_in[3];
    const float* br  = (const float*)d_in[4];
    const float* bi  = (const float*)d_in[5];
    const float* owr = (const float*)d_in[6];
    const float* owi = (const float*)d_in[7];
    const float* obr = (const float*)d_in[8];
    const float* obi = (const float*)d_in[9];
    float* out = (float*)d_out;

    const int SMEM = 65536;
    cudaFuncSetAttribute(k_gemm<0>, cudaFuncAttributeMaxDynamicSharedMemorySize, SMEM);
    cudaFuncSetAttribute(k_gemm<1>, cudaFuncAttributeMaxDynamicSharedMemorySize, SMEM);
    cudaFuncSetAttribute(k_gemm<2>, cudaFuncAttributeMaxDynamicSharedMemorySize, SMEM);
    cudaFuncSetAttribute(k_gemm<3>, cudaFuncAttributeMaxDynamicSharedMemorySize, SMEM);

    k_init<<<1, 1>>>();
    k_prep_x<<<32768, 256>>>(xr, xi);
    k_prep_w<<<49152, 256>>>(wr, wi);
    k_prep_ow<<<16384, 256>>>(owr, owi);

    k_gemm<0><<<dim3(48, 32), 256, SMEM>>>(nullptr, nullptr, nullptr, nullptr);
    k_trans_qk<<<16384, 256>>>(br, bi);
    k_trans_v<<<dim3(16, 64), 256>>>(br, bi);

    k_gemm<1><<<dim3(8, 8, 64), 256, SMEM>>>(nullptr, nullptr, nullptr, nullptr);
    k_scale<<<1, 1>>>();
    k_norm_aw<<<65536, 256>>>();

    k_gemm<2><<<dim3(1, 8, 64), 256, SMEM>>>(nullptr, nullptr, nullptr, nullptr);
    k_avg<<<16384, 256>>>(out + 2 * (size_t)SEG);
    k_split_attn<<<8192, 256>>>();

    k_gemm<3><<<dim3(16, 32), 256, SMEM>>>(obr, obi, out, out + SEG);
}